// round 1
// baseline (speedup 1.0000x reference)
#include <cuda_runtime.h>
#include <math.h>

#define NROWS 8192
#define DIM   1024
#define BM    128
#define BN    128
#define BK    16
#define JT    (NROWS / BN)   // 64 j-tiles

// Scratch (no allocations allowed in kernel_launch)
__device__ float g_inv1[NROWS];
__device__ float g_inv2[NROWS];
__device__ float g_diag[NROWS];
__device__ float g_pe[JT * NROWS];   // per-(jtile,row) partial sum of exp(m_ij)
__device__ float g_bl[NROWS / 128];  // per-block loss partials
__device__ float g_bp[NROWS / 128];  // per-block p partials

// ---------------------------------------------------------------------------
// 1) Row inverse norms: one warp per row, float4 loads, shfl reduce.
// ---------------------------------------------------------------------------
__global__ void norms_kernel(const float* __restrict__ z) {
    int warp = threadIdx.x >> 5;
    int lane = threadIdx.x & 31;
    int row  = blockIdx.x * 8 + warp;          // 2*NROWS rows total
    const float* p = z + (size_t)row * DIM;
    float s = 0.f;
    #pragma unroll
    for (int k = lane * 4; k < DIM; k += 128) {
        float4 v = *reinterpret_cast<const float4*>(p + k);
        s += v.x * v.x + v.y * v.y + v.z * v.z + v.w * v.w;
    }
    #pragma unroll
    for (int o = 16; o; o >>= 1) s += __shfl_xor_sync(0xffffffffu, s, o);
    if (lane == 0) {
        float inv = rsqrtf(s);
        if (row < NROWS) g_inv1[row] = inv;
        else             g_inv2[row - NROWS] = inv;
    }
}

// ---------------------------------------------------------------------------
// 2) Fused GEMM (x1 @ x2^T, cosine-scaled) + per-row exp-sum + diagonal.
//    128x128 tile, BK=16, 256 threads, 8x8 register micro-tile per thread.
//    Matrix is never written to memory.
// ---------------------------------------------------------------------------
__global__ __launch_bounds__(256) void gemm_kernel(const float* __restrict__ z) {
    __shared__ float smem[2 * BK * BM];   // As | Bs, reused for epilogue reduce
    float* As = smem;                     // [BK][BM]
    float* Bs = smem + BK * BM;           // [BK][BN]

    const float* x1 = z;
    const float* x2 = z + (size_t)NROWS * DIM;
    const int bi = blockIdx.y, bj = blockIdx.x;
    const int tid = threadIdx.x;
    const int tx = tid & 15, ty = tid >> 4;

    const float* Ag = x1 + (size_t)bi * BM * DIM;
    const float* Bg = x2 + (size_t)bj * BN * DIM;

    float acc[8][8];
    #pragma unroll
    for (int i = 0; i < 8; i++)
        #pragma unroll
        for (int j = 0; j < 8; j++) acc[i][j] = 0.f;

    for (int k0 = 0; k0 < DIM; k0 += BK) {
        // Load 128x16 A and B tiles, transposed into [BK][BM] layout.
        #pragma unroll
        for (int l = tid; l < 512; l += 256) {
            int row = l >> 2;
            int kq  = (l & 3) << 2;
            float4 a = *reinterpret_cast<const float4*>(Ag + (size_t)row * DIM + k0 + kq);
            As[(kq + 0) * BM + row] = a.x;
            As[(kq + 1) * BM + row] = a.y;
            As[(kq + 2) * BM + row] = a.z;
            As[(kq + 3) * BM + row] = a.w;
            float4 b = *reinterpret_cast<const float4*>(Bg + (size_t)row * DIM + k0 + kq);
            Bs[(kq + 0) * BM + row] = b.x;
            Bs[(kq + 1) * BM + row] = b.y;
            Bs[(kq + 2) * BM + row] = b.z;
            Bs[(kq + 3) * BM + row] = b.w;
        }
        __syncthreads();
        #pragma unroll
        for (int k = 0; k < BK; k++) {
            float a[8], b[8];
            *reinterpret_cast<float4*>(a)     = *reinterpret_cast<const float4*>(As + k * BM + ty * 8);
            *reinterpret_cast<float4*>(a + 4) = *reinterpret_cast<const float4*>(As + k * BM + ty * 8 + 4);
            *reinterpret_cast<float4*>(b)     = *reinterpret_cast<const float4*>(Bs + k * BM + tx * 8);
            *reinterpret_cast<float4*>(b + 4) = *reinterpret_cast<const float4*>(Bs + k * BM + tx * 8 + 4);
            #pragma unroll
            for (int i = 0; i < 8; i++)
                #pragma unroll
                for (int j = 0; j < 8; j++)
                    acc[i][j] = fmaf(a[i], b[j], acc[i][j]);
        }
        __syncthreads();
    }

    // Epilogue: scale to cosine sim (TAU=1), accumulate exp row-sums, grab diag.
    float inv1r[8], inv2r[8];
    #pragma unroll
    for (int i = 0; i < 8; i++) inv1r[i] = g_inv1[bi * BM + ty * 8 + i];
    #pragma unroll
    for (int j = 0; j < 8; j++) inv2r[j] = g_inv2[bj * BN + tx * 8 + j];

    const bool dthread = (bi == bj) && (tx == ty);
    float rse[8];
    #pragma unroll
    for (int i = 0; i < 8; i++) rse[i] = 0.f;
    #pragma unroll
    for (int i = 0; i < 8; i++) {
        #pragma unroll
        for (int j = 0; j < 8; j++) {
            float v = acc[i][j] * inv1r[i] * inv2r[j];
            rse[i] += __expf(v);
            if (dthread && i == j) g_diag[bi * BM + ty * 8 + i] = v;
        }
    }

    // Reduce across the 16 tx-threads that share each row (deterministic order).
    __syncthreads();   // smem reuse
    #pragma unroll
    for (int i = 0; i < 8; i++)
        smem[(ty * 8 + i) * 16 + tx] = rse[i];
    __syncthreads();
    if (tid < BM) {
        float se = 0.f;
        #pragma unroll
        for (int t = 0; t < 16; t++) se += smem[tid * 16 + t];
        g_pe[(size_t)bj * NROWS + bi * BM + tid] = se;
    }
}

// ---------------------------------------------------------------------------
// 3) Per-row finalize: p_ij, loss; block-level partial sums (fixed order).
//    ALPHA=1 -> alpha = p_ij.  BETA=0 -> neg_sim term drops entirely.
// ---------------------------------------------------------------------------
__global__ void finalize1_kernel() {
    int r = blockIdx.x * 128 + threadIdx.x;
    float se = 0.f;
    for (int t = 0; t < JT; t++) se += g_pe[(size_t)t * NROWS + r];
    float pos = g_diag[r];
    float pe  = __expf(pos);           // identical computation to epilogue term
    float p   = pe / (se - pe);
    float loss = -logf(p) - p * pos;

    __shared__ float sl[128], sp[128];
    sl[threadIdx.x] = loss;
    sp[threadIdx.x] = p;
    __syncthreads();
    #pragma unroll
    for (int o = 64; o; o >>= 1) {
        if (threadIdx.x < o) {
            sl[threadIdx.x] += sl[threadIdx.x + o];
            sp[threadIdx.x] += sp[threadIdx.x + o];
        }
        __syncthreads();
    }
    if (threadIdx.x == 0) {
        g_bl[blockIdx.x] = sl[0];
        g_bp[blockIdx.x] = sp[0];
    }
}

__global__ void finalize2_kernel(float* __restrict__ out) {
    __shared__ float sl[64], sp[64];
    int t = threadIdx.x;
    sl[t] = g_bl[t];
    sp[t] = g_bp[t];
    __syncthreads();
    #pragma unroll
    for (int o = 32; o; o >>= 1) {
        if (t < o) { sl[t] += sl[t + o]; sp[t] += sp[t + o]; }
        __syncthreads();
    }
    if (t == 0) {
        out[0] = sl[0] / (float)NROWS;   // loss.mean()
        out[1] = sp[0] / (float)NROWS;   // p_ij.mean()
    }
}

// ---------------------------------------------------------------------------
extern "C" void kernel_launch(void* const* d_in, const int* in_sizes, int n_in,
                              void* d_out, int out_size) {
    const float* z = (const float*)d_in[0];
    float* out = (float*)d_out;
    norms_kernel<<<2 * NROWS / 8, 256>>>(z);
    gemm_kernel<<<dim3(JT, NROWS / BM), 256>>>(z);
    finalize1_kernel<<<NROWS / 128, 128>>>();
    finalize2_kernel<<<1, 64>>>(out);
}

// round 3
// speedup vs baseline: 8.3351x; 8.3351x over previous
#include <cuda_runtime.h>
#include <cuda_bf16.h>
#include <math.h>
#include <stdint.h>

#define NROWS 8192
#define DIM   1024
#define BM    128
#define BN    128
#define BK    32
#define NSTAGE 4
#define NITER (DIM / BK)          // 32
#define JT    (NROWS / BN)        // 64
#define STAGE_A_BYTES (BM * BK * 2)          // 8192
#define STAGE_BYTES   (2 * STAGE_A_BYTES)    // 16384 (A | B)
#define SMEM_TOTAL    (NSTAGE * STAGE_BYTES) // 65536

// ---------------- device scratch ----------------
__device__ __align__(1024) __nv_bfloat16 g_zb[2 * NROWS * DIM];
__device__ float g_inv[2 * NROWS];
__device__ float g_diag[NROWS];
__device__ float g_pe[(size_t)JT * NROWS];
__device__ float g_bl[NROWS / 128];
__device__ float g_bp[NROWS / 128];

// ---------------- PTX helpers ----------------
__device__ __forceinline__ uint32_t smem_u32(const void* p) {
    uint32_t a;
    asm("{ .reg .u64 t; cvta.to.shared.u64 t, %1; cvt.u32.u64 %0, t; }" : "=r"(a) : "l"(p));
    return a;
}
#define CPA16(dst, src) \
    asm volatile("cp.async.cg.shared.global [%0], [%1], 16;" :: "r"(dst), "l"(src) : "memory")
#define CPA_COMMIT() asm volatile("cp.async.commit_group;" ::: "memory")
#define CPA_WAIT2()  asm volatile("cp.async.wait_group 2;" ::: "memory")

__device__ __forceinline__ void ldsm4(uint32_t* r, uint32_t addr) {
    asm volatile("ldmatrix.sync.aligned.m8n8.x4.shared.b16 {%0,%1,%2,%3}, [%4];"
        : "=r"(r[0]), "=r"(r[1]), "=r"(r[2]), "=r"(r[3]) : "r"(addr));
}
__device__ __forceinline__ void mma16816(float* d, const uint32_t* a, const uint32_t* b) {
    asm volatile(
        "mma.sync.aligned.m16n8k16.row.col.f32.bf16.bf16.f32 "
        "{%0,%1,%2,%3}, {%4,%5,%6,%7}, {%8,%9}, {%0,%1,%2,%3};"
        : "+f"(d[0]), "+f"(d[1]), "+f"(d[2]), "+f"(d[3])
        : "r"(a[0]), "r"(a[1]), "r"(a[2]), "r"(a[3]), "r"(b[0]), "r"(b[1]));
}

// ---------------------------------------------------------------------------
// 1) Row inverse norms
// ---------------------------------------------------------------------------
__global__ void norms_kernel(const float* __restrict__ z) {
    int warp = threadIdx.x >> 5, lane = threadIdx.x & 31;
    int row  = blockIdx.x * 8 + warp;
    const float* p = z + (size_t)row * DIM;
    float s = 0.f;
    #pragma unroll
    for (int k = lane * 4; k < DIM; k += 128) {
        float4 v = *reinterpret_cast<const float4*>(p + k);
        s += v.x * v.x + v.y * v.y + v.z * v.z + v.w * v.w;
    }
    #pragma unroll
    for (int o = 16; o; o >>= 1) s += __shfl_xor_sync(0xffffffffu, s, o);
    if (lane == 0) g_inv[row] = rsqrtf(s);
}

// ---------------------------------------------------------------------------
// 2) Convert to pre-normalized bf16
// ---------------------------------------------------------------------------
__global__ void convert_kernel(const float* __restrict__ z) {
    size_t i = (size_t)(blockIdx.x * blockDim.x + threadIdx.x) * 4;
    float4 v = *reinterpret_cast<const float4*>(z + i);
    float inv = g_inv[i >> 10];
    __nv_bfloat162* o = reinterpret_cast<__nv_bfloat162*>(g_zb + i);
    o[0] = __floats2bfloat162_rn(v.x * inv, v.y * inv);
    o[1] = __floats2bfloat162_rn(v.z * inv, v.w * inv);
}

// ---------------------------------------------------------------------------
// 3) HMMA GEMM 128x128x32, 4-stage cp.async, fused exp epilogue
// ---------------------------------------------------------------------------
__global__ __launch_bounds__(256, 2) void gemm_kernel() {
    extern __shared__ char smem[];
    const uint32_t sb = smem_u32(smem);
    const int tid = threadIdx.x;
    const int warp = tid >> 5, lane = tid & 31;
    const int wy = warp >> 2, wx = warp & 3;        // 2 x 4 warp grid
    const int bi = blockIdx.y, bj = blockIdx.x;

    const char* Ag = (const char*)(g_zb + (size_t)bi * BM * DIM);
    const char* Bg = (const char*)(g_zb + (size_t)(NROWS + bj * BN) * DIM);

    // cp.async per-thread mapping: chunk c = tid (+256); row=c/4, ch=c%4
    const int row0 = tid >> 2, ch0 = tid & 3;
    const int ph0  = ch0 ^ ((row0 >> 1) & 3);
    const uint32_t s_off0 = row0 * 64 + ph0 * 16;          // same phys for row0+64
    const size_t   g_off0 = ((size_t)row0 * DIM + ch0 * 8) * 2;
    const size_t   g_row64 = (size_t)64 * DIM * 2;

    float acc[4][4][4];
    #pragma unroll
    for (int mt = 0; mt < 4; mt++)
        #pragma unroll
        for (int nt = 0; nt < 4; nt++)
            #pragma unroll
            for (int q = 0; q < 4; q++) acc[mt][nt][q] = 0.f;

    // prologue: stages 0..2
    #pragma unroll
    for (int s = 0; s < NSTAGE - 1; s++) {
        uint32_t As = sb + s * STAGE_BYTES;
        uint32_t Bs = As + STAGE_A_BYTES;
        size_t kb = (size_t)(s * BK) * 2;
        CPA16(As + s_off0,             Ag + g_off0 + kb);
        CPA16(As + s_off0 + 64 * 64,   Ag + g_off0 + g_row64 + kb);
        CPA16(Bs + s_off0,             Bg + g_off0 + kb);
        CPA16(Bs + s_off0 + 64 * 64,   Bg + g_off0 + g_row64 + kb);
        CPA_COMMIT();
    }

    // frag address components (lane-invariant parts)
    const int rl = lane & 15;                  // A row within 16
    const int ahi = lane >> 4;                 // A chunk select
    const int asw = (rl >> 1) & 3;
    const int nl = (lane & 7) | ((lane >> 4) << 3);   // B n-row within 16
    const int bhi = (lane >> 3) & 1;
    const int bsw = (nl >> 1) & 3;

    for (int kc = 0; kc < NITER; kc++) {
        const int st = kc & (NSTAGE - 1);
        CPA_WAIT2();
        __syncthreads();
        if (kc + NSTAGE - 1 < NITER) {
            const int sn = (kc + NSTAGE - 1) & (NSTAGE - 1);
            uint32_t As = sb + sn * STAGE_BYTES;
            uint32_t Bs = As + STAGE_A_BYTES;
            size_t kb = (size_t)((kc + NSTAGE - 1) * BK) * 2;
            CPA16(As + s_off0,           Ag + g_off0 + kb);
            CPA16(As + s_off0 + 64 * 64, Ag + g_off0 + g_row64 + kb);
            CPA16(Bs + s_off0,           Bg + g_off0 + kb);
            CPA16(Bs + s_off0 + 64 * 64, Bg + g_off0 + g_row64 + kb);
            CPA_COMMIT();
        }
        const uint32_t As = sb + st * STAGE_BYTES;
        const uint32_t Bs = As + STAGE_A_BYTES;
        #pragma unroll
        for (int ks = 0; ks < 2; ks++) {
            uint32_t a[4][4], b[2][4];
            uint32_t a_addr = As + (wy * 64 + rl) * 64 + (((ks * 2 + ahi) ^ asw) * 16);
            #pragma unroll
            for (int mt = 0; mt < 4; mt++) ldsm4(a[mt], a_addr + mt * 1024);
            uint32_t b_addr = Bs + (wx * 32 + nl) * 64 + (((ks * 2 + bhi) ^ bsw) * 16);
            #pragma unroll
            for (int p = 0; p < 2; p++) ldsm4(b[p], b_addr + p * 1024);
            #pragma unroll
            for (int mt = 0; mt < 4; mt++)
                #pragma unroll
                for (int nt = 0; nt < 4; nt++)
                    mma16816(acc[mt][nt], a[mt], &b[nt >> 1][(nt & 1) * 2]);
        }
        __syncthreads();
    }

    // ---------------- epilogue: exp row-sums + diagonal ----------------
    __syncthreads();
    float* sred = (float*)smem;                // 128 rows x 4 wx
    const bool isdiag = (bi == bj);
    #pragma unroll
    for (int mt = 0; mt < 4; mt++) {
        int ra = wy * 64 + mt * 16 + (lane >> 2);
        float sA = 0.f, sB = 0.f;
        #pragma unroll
        for (int nt = 0; nt < 4; nt++) {
            int c0 = wx * 32 + nt * 8 + 2 * (lane & 3);
            float v0 = acc[mt][nt][0], v1 = acc[mt][nt][1];
            float v2 = acc[mt][nt][2], v3 = acc[mt][nt][3];
            sA += __expf(v0) + __expf(v1);
            sB += __expf(v2) + __expf(v3);
            if (isdiag) {
                if (ra == c0)         g_diag[bi * BM + ra] = v0;
                if (ra == c0 + 1)     g_diag[bi * BM + ra] = v1;
                if (ra + 8 == c0)     g_diag[bi * BM + ra + 8] = v2;
                if (ra + 8 == c0 + 1) g_diag[bi * BM + ra + 8] = v3;
            }
        }
        sA += __shfl_xor_sync(0xffffffffu, sA, 1);
        sA += __shfl_xor_sync(0xffffffffu, sA, 2);
        sB += __shfl_xor_sync(0xffffffffu, sB, 1);
        sB += __shfl_xor_sync(0xffffffffu, sB, 2);
        if ((lane & 3) == 0) {
            sred[ra * 4 + wx] = sA;
            sred[(ra + 8) * 4 + wx] = sB;
        }
    }
    __syncthreads();
    if (tid < BM) {
        float s = sred[tid * 4 + 0] + sred[tid * 4 + 1]
                + sred[tid * 4 + 2] + sred[tid * 4 + 3];
        g_pe[(size_t)bj * NROWS + bi * BM + tid] = s;
    }
}

// ---------------------------------------------------------------------------
// 4) Finalize (ALPHA=1 -> alpha=p_ij, BETA=0 -> neg_sim drops)
// ---------------------------------------------------------------------------
__global__ void finalize1_kernel() {
    int r = blockIdx.x * 128 + threadIdx.x;
    float se = 0.f;
    #pragma unroll 8
    for (int t = 0; t < JT; t++) se += g_pe[(size_t)t * NROWS + r];
    float pos = g_diag[r];
    float pe  = __expf(pos);                   // bitwise-identical to epilogue term
    float p   = pe / (se - pe);
    float loss = -logf(p) - p * pos;

    __shared__ float sl[128], sp[128];
    sl[threadIdx.x] = loss;
    sp[threadIdx.x] = p;
    __syncthreads();
    #pragma unroll
    for (int o = 64; o; o >>= 1) {
        if (threadIdx.x < o) {
            sl[threadIdx.x] += sl[threadIdx.x + o];
            sp[threadIdx.x] += sp[threadIdx.x + o];
        }
        __syncthreads();
    }
    if (threadIdx.x == 0) { g_bl[blockIdx.x] = sl[0]; g_bp[blockIdx.x] = sp[0]; }
}

__global__ void finalize2_kernel(float* __restrict__ out) {
    __shared__ float sl[64], sp[64];
    int t = threadIdx.x;
    sl[t] = g_bl[t];
    sp[t] = g_bp[t];
    __syncthreads();
    #pragma unroll
    for (int o = 32; o; o >>= 1) {
        if (t < o) { sl[t] += sl[t + o]; sp[t] += sp[t + o]; }
        __syncthreads();
    }
    if (t == 0) {
        out[0] = sl[0] / (float)NROWS;
        out[1] = sp[0] / (float)NROWS;
    }
}

// ---------------------------------------------------------------------------
extern "C" void kernel_launch(void* const* d_in, const int* in_sizes, int n_in,
                              void* d_out, int out_size) {
    const float* z = (const float*)d_in[0];
    float* out = (float*)d_out;

    cudaFuncSetAttribute(gemm_kernel, cudaFuncAttributeMaxDynamicSharedMemorySize, SMEM_TOTAL);

    norms_kernel<<<2 * NROWS / 8, 256>>>(z);
    convert_kernel<<<(2 * NROWS * DIM / 4) / 256, 256>>>(z);
    gemm_kernel<<<dim3(NROWS / BN, NROWS / BM), 256, SMEM_TOTAL>>>();
    finalize1_kernel<<<NROWS / 128, 128>>>();
    finalize2_kernel<<<1, 64>>>(out);
}